// round 11
// baseline (speedup 1.0000x reference)
#include <cuda_runtime.h>
#include <cstdint>
#include <math.h>

#define K1T 1152
#define K2T 2432
#define NCH1 36
#define NCH2 76
#define PH 66
#define PIX (PH*PH)

__device__ float g_y[(size_t)32 * PIX * 256];
__device__ float g_xr[(size_t)32 * PIX * 128];
__device__ float g_sq[131072];
__device__ float g_asum[131072];
__device__ float g_wyT[256 * K1T];
__device__ float g_wlT[256 * K2T];
__device__ float g_bsum[256];

__device__ __forceinline__ uint32_t smem_u32(const void* p) {
    uint32_t a;
    asm("{ .reg .u64 t; cvta.to.shared.u64 t, %1; cvt.u32.u64 %0, t; }" : "=r"(a) : "l"(p));
    return a;
}
__device__ __forceinline__ float tf32r(float f) {
    uint32_t u; asm("cvt.rna.tf32.f32 %0, %1;" : "=r"(u) : "f"(f));
    return __uint_as_float(u);
}
__device__ __forceinline__ int kperm(int k) {
    const int ks = (k >> 3) & 3, c = k & 3, hi = (k >> 2) & 1;
    return (k & ~31) | ((4 * ks + c) * 2 + hi);
}
__device__ __forceinline__ void cpa16(uint32_t dst, const float* src) {
    asm volatile("cp.async.cg.shared.global [%0], [%1], 16;" :: "r"(dst), "l"(src));
}
#define CPA_COMMIT()  asm volatile("cp.async.commit_group;" ::: "memory")
#define CPA_WAIT1()   asm volatile("cp.async.wait_group 1;" ::: "memory")
#define CPA_WAIT0()   asm volatile("cp.async.wait_group 0;" ::: "memory")

__device__ __forceinline__ void mma8(float* d, uint32_t a0, uint32_t a1, uint32_t a2, uint32_t a3,
                                     uint32_t b0, uint32_t b1) {
    asm volatile("mma.sync.aligned.m16n8k8.row.col.f32.tf32.tf32.f32 "
                 "{%0,%1,%2,%3}, {%4,%5,%6,%7}, {%8,%9}, {%0,%1,%2,%3};"
                 : "+f"(d[0]), "+f"(d[1]), "+f"(d[2]), "+f"(d[3])
                 : "r"(a0), "r"(a1), "r"(a2), "r"(a3), "r"(b0), "r"(b1));
}

// Warp tile 64(m) x 32(n). Fragments per ks: 8 A float2 + 4 B float2.
__device__ __forceinline__ void ldfrag(const char* As, const char* Bs, int ks, int lane,
                                       int wm, int wn, float2* aL, float2* aH, float2* bv)
{
    const int r = lane >> 2, c = lane & 3;
    const int u = ((4 * ks + c) ^ (4 * (r & 3))) * 8;
    #pragma unroll
    for (int mi = 0; mi < 4; mi++) {
        const int row0 = wm * 64 + mi * 16 + r;
        aL[mi] = *(const float2*)(As + row0 * 128 + u);
        aH[mi] = *(const float2*)(As + (row0 + 8) * 128 + u);
    }
    #pragma unroll
    for (int ni = 0; ni < 4; ni++)
        bv[ni] = *(const float2*)(Bs + (wn * 32 + ni * 8 + r) * 128 + u);
}
__device__ __forceinline__ void do_mmas(float acc[4][4][4], const float2* aL, const float2* aH,
                                        const float2* bv)
{
    #pragma unroll
    for (int ni = 0; ni < 4; ni++)
        #pragma unroll
        for (int mi = 0; mi < 4; mi++)
            mma8(acc[mi][ni], __float_as_uint(aL[mi].x), __float_as_uint(aH[mi].x),
                 __float_as_uint(aL[mi].y), __float_as_uint(aH[mi].y),
                 __float_as_uint(bv[ni].x), __float_as_uint(bv[ni].y));
}

__device__ __forceinline__ size_t padpix(int m) {
    const int n = m >> 12, h = (m >> 6) & 63, w = m & 63;
    return (size_t)((n * PH + h + 1) * PH + (w + 1));
}

// ---- prep ----
__global__ __launch_bounds__(256)
void k0a_w(const float* __restrict__ wy, const float* __restrict__ wl, const float* __restrict__ wp)
{
    const int co = blockIdx.x, t = threadIdx.x;
    __shared__ float red[256];
    float s = 0.f;
    for (int k = t; k < K1T; k += 256) {
        float v = wy[(size_t)k * 256 + co];
        s += v * v;
        g_wyT[(size_t)co * K1T + kperm(k)] = tf32r(v);
    }
    red[t] = s; __syncthreads();
    for (int o = 128; o > 0; o >>= 1) { if (t < o) red[t] += red[t + o]; __syncthreads(); }
    if (t == 0) g_bsum[co] = red[0];
    for (int k = t; k < K2T; k += 256) {
        float v = (k < 2304) ? wl[(size_t)k * 256 + co] : wp[(size_t)(k - 2304) * 256 + co];
        g_wlT[(size_t)co * K2T + kperm(k)] = tf32r(v);
    }
}
__global__ __launch_bounds__(256)
void k0b_x(const float* __restrict__ x)
{
    const int p = blockIdx.x * 8 + (threadIdx.x >> 5), lane = threadIdx.x & 31;
    float4 v = *(const float4*)(x + (size_t)p * 128 + lane * 4);
    float s = v.x * v.x + v.y * v.y + v.z * v.z + v.w * v.w;
    #pragma unroll
    for (int o = 16; o > 0; o >>= 1) s += __shfl_xor_sync(0xffffffff, s, o);
    if (lane == 0) g_sq[p] = s;
    float* dst = g_xr + padpix(p) * 128;
    const int ch = lane * 4;
    dst[kperm(ch)]     = tf32r(v.x);
    dst[kperm(ch + 1)] = tf32r(v.y);
    dst[kperm(ch + 2)] = tf32r(v.z);
    dst[kperm(ch + 3)] = tf32r(v.w);
}
__global__ __launch_bounds__(256)
void k0c_asum()
{
    const int p = blockIdx.x * 256 + threadIdx.x;
    const int h = (p >> 6) & 63, w = p & 63;
    float s = 0.f;
    #pragma unroll
    for (int dh = -1; dh <= 1; dh++)
        #pragma unroll
        for (int dw = -1; dw <= 1; dw++) {
            int hh = h + dh, ww = w + dw;
            if ((unsigned)hh < 64u && (unsigned)ww < 64u) s += g_sq[p + dh * 64 + dw];
        }
    g_asum[p] = s;
}

// ---- k1: 256 threads, warp grid 2m x 4n, warp tile 64x32 ----
__global__ __launch_bounds__(256, 2)
void k1_yat(const float* __restrict__ alphap)
{
    extern __shared__ float smf[];
    const uint32_t sb = smem_u32(smf);
    const int tid = threadIdx.x, lane = tid & 31, wid = tid >> 5;
    const int wm = wid >> 2, wn = wid & 3;
    const int m_base = blockIdx.y * 128, c_base = blockIdx.x * 128;
    float* sbsum = smf + 24576;
    if (tid < 128) sbsum[tid] = g_bsum[c_base + tid];

    float acc[4][4][4];
    #pragma unroll
    for (int mi = 0; mi < 4; mi++)
        #pragma unroll
        for (int ni = 0; ni < 4; ni++)
            #pragma unroll
            for (int e = 0; e < 4; e++) acc[mi][ni][e] = 0.f;

    const int t8 = tid & 7, row0 = tid >> 3;   // row0 0..31
    const float* xb[4];
    #pragma unroll
    for (int p = 0; p < 4; p++)
        xb[p] = g_xr + padpix(m_base + row0 + 32 * p) * 128 + t8 * 4;
    const float* wb0 = g_wyT + (size_t)(c_base + row0) * K1T + t8 * 4;
    const uint32_t du0 = (uint32_t)(row0 * 128 + ((t8 ^ (2 * (row0 & 3))) * 16));

    auto stage = [&](int c, int b) {
        const int khw = c >> 2, c0 = (c & 3) * 32;
        const int dh = khw / 3 - 1, dw = khw % 3 - 1;
        const int xoff = (dh * PH + dw) * 128 + c0;
        const uint32_t base = sb + (uint32_t)b * 32768u + du0;
        const float* wsrc = wb0 + c * 32;
        #pragma unroll
        for (int p = 0; p < 4; p++) {
            cpa16(base + p * 4096u, xb[p] + xoff);
            cpa16(base + 16384u + p * 4096u, wsrc + p * (32 * K1T));
        }
        CPA_COMMIT();
    };

    stage(0, 0); stage(1, 1);
    CPA_WAIT1(); __syncthreads();
    float2 aL[2][4], aH[2][4], bv[2][4];
    ldfrag((const char*)smf, (const char*)smf + 16384, 0, lane, wm, wn, aL[0], aH[0], bv[0]);

    int b = 0;
    for (int c = 0; c < NCH1; c++) {
        const char* As = (const char*)smf + b * 32768;
        const char* Bs = As + 16384;
        #pragma unroll
        for (int ks = 0; ks < 3; ks++) {
            ldfrag(As, Bs, ks + 1, lane, wm, wn, aL[(ks + 1) & 1], aH[(ks + 1) & 1], bv[(ks + 1) & 1]);
            do_mmas(acc, aL[ks & 1], aH[ks & 1], bv[ks & 1]);
        }
        if (c + 1 < NCH1) {
            CPA_WAIT0(); __syncthreads();
            int b2 = b + 2; if (b2 >= 3) b2 -= 3;
            if (c + 2 < NCH1) stage(c + 2, b2);
            int nb = b + 1; if (nb >= 3) nb -= 3;
            const char* As2 = (const char*)smf + nb * 32768;
            ldfrag(As2, As2 + 16384, 0, lane, wm, wn, aL[0], aH[0], bv[0]);
        }
        do_mmas(acc, aL[1], aH[1], bv[1]);
        if (++b == 3) b = 0;
    }

    const float scale = powf(16.f / log1pf(256.f), alphap[0]);
    #pragma unroll
    for (int mi = 0; mi < 4; mi++) {
        const int r0 = wm * 64 + mi * 16 + (lane >> 2);
        const int m0 = m_base + r0, m1 = m0 + 8;
        const float as0 = g_asum[m0], as1 = g_asum[m1];
        float* y0 = g_y + padpix(m0) * 256 + c_base;
        float* y1 = g_y + padpix(m1) * 256 + c_base;
        #pragma unroll
        for (int ni = 0; ni < 4; ni++) {
            const int cl = wn * 32 + ni * 8 + (lane & 3) * 2;
            const float bs0 = sbsum[cl], bs1 = sbsum[cl + 1];
            const float* d = acc[mi][ni];
            const int p0 = kperm(cl), p1 = kperm(cl + 1);
            y0[p0] = tf32r(d[0] * d[0] / (as0 + bs0 - 2.f * d[0] + 1e-5f) * scale);
            y0[p1] = tf32r(d[1] * d[1] / (as0 + bs1 - 2.f * d[1] + 1e-5f) * scale);
            y1[p0] = tf32r(d[2] * d[2] / (as1 + bs0 - 2.f * d[2] + 1e-5f) * scale);
            y1[p1] = tf32r(d[3] * d[3] / (as1 + bs1 - 2.f * d[3] + 1e-5f) * scale);
        }
    }
}

// ---- k2: 256 threads, warp tile 64x32 ----
__global__ __launch_bounds__(256, 2)
void k2_lin(float* __restrict__ out)
{
    extern __shared__ float smf[];
    const uint32_t sb = smem_u32(smf);
    const int tid = threadIdx.x, lane = tid & 31, wid = tid >> 5;
    const int wm = wid >> 2, wn = wid & 3;
    const int m_base = blockIdx.y * 128, c_base = blockIdx.x * 128;

    float acc[4][4][4];
    #pragma unroll
    for (int mi = 0; mi < 4; mi++)
        #pragma unroll
        for (int ni = 0; ni < 4; ni++)
            #pragma unroll
            for (int e = 0; e < 4; e++) acc[mi][ni][e] = 0.f;

    const int t8 = tid & 7, row0 = tid >> 3;
    const float *yb[4], *xb2[4];
    #pragma unroll
    for (int p = 0; p < 4; p++) {
        const size_t pp = padpix(m_base + row0 + 32 * p);
        yb[p]  = g_y  + pp * 256 + t8 * 4;
        xb2[p] = g_xr + pp * 128 + t8 * 4;
    }
    const float* wb0 = g_wlT + (size_t)(c_base + row0) * K2T + t8 * 4;
    const uint32_t du0 = (uint32_t)(row0 * 128 + ((t8 ^ (2 * (row0 & 3))) * 16));

    auto stage = [&](int c, int b) {
        const uint32_t base = sb + (uint32_t)b * 32768u + du0;
        const float* wsrc = wb0 + c * 32;
        if (c < 72) {
            const int khw = c >> 3, c0 = (c & 7) * 32;
            const int dh = khw / 3 - 1, dw = khw % 3 - 1;
            const int yoff = (dh * PH + dw) * 256 + c0;
            #pragma unroll
            for (int p = 0; p < 4; p++) {
                cpa16(base + p * 4096u, yb[p] + yoff);
                cpa16(base + 16384u + p * 4096u, wsrc + p * (32 * K2T));
            }
        } else {
            const int c0 = (c - 72) * 32;
            #pragma unroll
            for (int p = 0; p < 4; p++) {
                cpa16(base + p * 4096u, xb2[p] + c0);
                cpa16(base + 16384u + p * 4096u, wsrc + p * (32 * K2T));
            }
        }
        CPA_COMMIT();
    };

    stage(0, 0); stage(1, 1);
    CPA_WAIT1(); __syncthreads();
    float2 aL[2][4], aH[2][4], bv[2][4];
    ldfrag((const char*)smf, (const char*)smf + 16384, 0, lane, wm, wn, aL[0], aH[0], bv[0]);

    int b = 0;
    for (int c = 0; c < NCH2; c++) {
        const char* As = (const char*)smf + b * 32768;
        const char* Bs = As + 16384;
        #pragma unroll
        for (int ks = 0; ks < 3; ks++) {
            ldfrag(As, Bs, ks + 1, lane, wm, wn, aL[(ks + 1) & 1], aH[(ks + 1) & 1], bv[(ks + 1) & 1]);
            do_mmas(acc, aL[ks & 1], aH[ks & 1], bv[ks & 1]);
        }
        if (c + 1 < NCH2) {
            CPA_WAIT0(); __syncthreads();
            int b2 = b + 2; if (b2 >= 3) b2 -= 3;
            if (c + 2 < NCH2) stage(c + 2, b2);
            int nb = b + 1; if (nb >= 3) nb -= 3;
            const char* As2 = (const char*)smf + nb * 32768;
            ldfrag(As2, As2 + 16384, 0, lane, wm, wn, aL[0], aH[0], bv[0]);
        }
        do_mmas(acc, aL[1], aH[1], bv[1]);
        if (++b == 3) b = 0;
    }

    __syncthreads();
    #pragma unroll
    for (int mi = 0; mi < 4; mi++) {
        const int r0 = wm * 64 + mi * 16 + (lane >> 2);
        #pragma unroll
        for (int ni = 0; ni < 4; ni++) {
            const int cl = wn * 32 + ni * 8 + (lane & 3) * 2;
            const float* d = acc[mi][ni];
            *(float2*)(smf + r0 * 132 + cl) = make_float2(d[0], d[1]);
            *(float2*)(smf + (r0 + 8) * 132 + cl) = make_float2(d[2], d[3]);
        }
    }
    __syncthreads();
    const int n = m_base >> 12, hp = ((m_base >> 6) & 63) >> 1;
    #pragma unroll
    for (int it = 0; it < 4; it++) {
        const int idx = tid + it * 256, pw = idx >> 5, ch = (idx & 31) * 4;
        float4 a0 = *(const float4*)(smf + (2 * pw) * 132 + ch);
        float4 a1 = *(const float4*)(smf + (2 * pw + 1) * 132 + ch);
        float4 a2 = *(const float4*)(smf + (64 + 2 * pw) * 132 + ch);
        float4 a3 = *(const float4*)(smf + (64 + 2 * pw + 1) * 132 + ch);
        *(float4*)(out + ((size_t)((n * 32 + hp) * 32 + pw)) * 256 + c_base + ch) =
            make_float4(0.25f * (a0.x + a1.x + a2.x + a3.x), 0.25f * (a0.y + a1.y + a2.y + a3.y),
                        0.25f * (a0.z + a1.z + a2.z + a3.z), 0.25f * (a0.w + a1.w + a2.w + a3.w));
    }
}

extern "C" void kernel_launch(void* const* d_in, const int* in_sizes, int n_in,
                              void* d_out, int out_size)
{
    const float* x  = (const float*)d_in[0];
    const float* wy = (const float*)d_in[1];
    const float* al = (const float*)d_in[2];
    const float* wl = (const float*)d_in[3];
    const float* wp = (const float*)d_in[4];
    float* out = (float*)d_out;

    cudaFuncSetAttribute(k1_yat, cudaFuncAttributeMaxDynamicSharedMemorySize, 98816);
    cudaFuncSetAttribute(k2_lin, cudaFuncAttributeMaxDynamicSharedMemorySize, 98304);

    k0a_w<<<256, 256>>>(wy, wl, wp);
    k0b_x<<<16384, 256>>>(x);
    k0c_asum<<<512, 256>>>();
    k1_yat<<<dim3(2, 1024), 256, 98816>>>(al);
    k2_lin<<<dim3(2, 1024), 256, 98304>>>(out);
}

// round 12
// speedup vs baseline: 1.6861x; 1.6861x over previous
#include <cuda_runtime.h>
#include <cuda_fp16.h>
#include <cstdint>
#include <math.h>

#define K1T 1152
#define K2T 2432
#define NCH1 36
#define NCH2 38          // 38 chunks of 64 k (36 conv + 2 residual)
#define PH 66
#define PIX (PH*PH)

__device__ uint32_t g_yh[(size_t)32 * PIX * 128];   // half2 per 2 channels, halo-padded
__device__ float    g_xr[(size_t)32 * PIX * 128];   // tf32 for k1, halo-padded
__device__ __half   g_xh[(size_t)32 * PIX * 128];   // fp16 for k2 residual, halo-padded
__device__ float    g_sq[131072];
__device__ float    g_asum[131072];
__device__ float    g_wyT[256 * K1T];               // tf32, kperm
__device__ __half   g_wlh[256 * K2T];               // fp16, fperm
__device__ float    g_bsum[256];

__device__ __forceinline__ uint32_t smem_u32(const void* p) {
    uint32_t a;
    asm("{ .reg .u64 t; cvta.to.shared.u64 t, %1; cvt.u32.u64 %0, t; }" : "=r"(a) : "l"(p));
    return a;
}
__device__ __forceinline__ float tf32r(float f) {
    uint32_t u; asm("cvt.rna.tf32.f32 %0, %1;" : "=r"(u) : "f"(f));
    return __uint_as_float(u);
}
// tf32 per-32 chunk perm: k = ks*8 + c + 4*hi -> float2 slot 4*ks+c, hi = .y
__device__ __forceinline__ int kperm(int k) {
    const int ks = (k >> 3) & 3, c = k & 3, hi = (k >> 2) & 1;
    return (k & ~31) | ((4 * ks + c) * 2 + hi);
}
// fp16 per-64 chunk perm on channel-pairs: unit u (=k>>1) -> b32 pos 8m+2(t&3)+(t>>2)
__device__ __forceinline__ int fperm(int k) {
    const int u = (k >> 1) & 31, m = u >> 3, t = u & 7;
    return (k & ~63) + (m * 8 + (t & 3) * 2 + (t >> 2)) * 2 + (k & 1);
}
__device__ __forceinline__ void cpa16(uint32_t dst, const void* src) {
    asm volatile("cp.async.cg.shared.global [%0], [%1], 16;" :: "r"(dst), "l"(src));
}
#define CPA_COMMIT()  asm volatile("cp.async.commit_group;" ::: "memory")
#define CPA_WAIT1()   asm volatile("cp.async.wait_group 1;" ::: "memory")
#define CPA_WAIT0()   asm volatile("cp.async.wait_group 0;" ::: "memory")

__device__ __forceinline__ void mma8(float* d, uint32_t a0, uint32_t a1, uint32_t a2, uint32_t a3,
                                     uint32_t b0, uint32_t b1) {
    asm volatile("mma.sync.aligned.m16n8k8.row.col.f32.tf32.tf32.f32 "
                 "{%0,%1,%2,%3}, {%4,%5,%6,%7}, {%8,%9}, {%0,%1,%2,%3};"
                 : "+f"(d[0]), "+f"(d[1]), "+f"(d[2]), "+f"(d[3])
                 : "r"(a0), "r"(a1), "r"(a2), "r"(a3), "r"(b0), "r"(b1));
}
__device__ __forceinline__ void mmah(float* d, uint32_t a0, uint32_t a1, uint32_t a2, uint32_t a3,
                                     uint32_t b0, uint32_t b1) {
    asm volatile("mma.sync.aligned.m16n8k16.row.col.f32.f16.f16.f32 "
                 "{%0,%1,%2,%3}, {%4,%5,%6,%7}, {%8,%9}, {%0,%1,%2,%3};"
                 : "+f"(d[0]), "+f"(d[1]), "+f"(d[2]), "+f"(d[3])
                 : "r"(a0), "r"(a1), "r"(a2), "r"(a3), "r"(b0), "r"(b1));
}

// Shared addressing for both dtypes: As/Bs 128 rows x 128B; 8B unit s at s^(4*(r&3)).
__device__ __forceinline__ void ldfrag(const char* As, const char* Bs, int ks, int lane,
                                       int wm, int wn, uint2* aL, uint2* aH, uint2* bv)
{
    const int r = lane >> 2, c = lane & 3;
    const int u = ((4 * ks + c) ^ (4 * (r & 3))) * 8;
    #pragma unroll
    for (int mi = 0; mi < 4; mi++) {
        const int row0 = wm * 64 + mi * 16 + r;
        aL[mi] = *(const uint2*)(As + row0 * 128 + u);
        aH[mi] = *(const uint2*)(As + (row0 + 8) * 128 + u);
    }
    #pragma unroll
    for (int ni = 0; ni < 8; ni++)
        bv[ni] = *(const uint2*)(Bs + (wn * 64 + ni * 8 + r) * 128 + u);
}
__device__ __forceinline__ void do_mmas_t(float acc[4][8][4], const uint2* aL, const uint2* aH,
                                          const uint2* bv)
{
    #pragma unroll
    for (int ni = 0; ni < 8; ni++)
        #pragma unroll
        for (int mi = 0; mi < 4; mi++)
            mma8(acc[mi][ni], aL[mi].x, aH[mi].x, aL[mi].y, aH[mi].y, bv[ni].x, bv[ni].y);
}
__device__ __forceinline__ void do_mmas_h(float acc[4][8][4], const uint2* aL, const uint2* aH,
                                          const uint2* bv)
{
    #pragma unroll
    for (int ni = 0; ni < 8; ni++)
        #pragma unroll
        for (int mi = 0; mi < 4; mi++)
            mmah(acc[mi][ni], aL[mi].x, aH[mi].x, aL[mi].y, aH[mi].y, bv[ni].x, bv[ni].y);
}

__device__ __forceinline__ size_t padpix(int m) {
    const int n = m >> 12, h = (m >> 6) & 63, w = m & 63;
    return (size_t)((n * PH + h + 1) * PH + (w + 1));
}

// ---- prep ----
__global__ __launch_bounds__(256)
void k0a_w(const float* __restrict__ wy, const float* __restrict__ wl, const float* __restrict__ wp)
{
    const int co = blockIdx.x, t = threadIdx.x;
    __shared__ float red[256];
    float s = 0.f;
    for (int k = t; k < K1T; k += 256) {
        float v = wy[(size_t)k * 256 + co];
        s += v * v;
        g_wyT[(size_t)co * K1T + kperm(k)] = tf32r(v);
    }
    red[t] = s; __syncthreads();
    for (int o = 128; o > 0; o >>= 1) { if (t < o) red[t] += red[t + o]; __syncthreads(); }
    if (t == 0) g_bsum[co] = red[0];
    for (int k = t; k < K2T; k += 256) {
        float v = (k < 2304) ? wl[(size_t)k * 256 + co] : wp[(size_t)(k - 2304) * 256 + co];
        g_wlh[(size_t)co * K2T + fperm(k)] = __float2half_rn(v);
    }
}
__global__ __launch_bounds__(256)
void k0b_x(const float* __restrict__ x)
{
    const int p = blockIdx.x * 8 + (threadIdx.x >> 5), lane = threadIdx.x & 31;
    float4 v = *(const float4*)(x + (size_t)p * 128 + lane * 4);
    float s = v.x * v.x + v.y * v.y + v.z * v.z + v.w * v.w;
    #pragma unroll
    for (int o = 16; o > 0; o >>= 1) s += __shfl_xor_sync(0xffffffff, s, o);
    if (lane == 0) g_sq[p] = s;
    const size_t pp = padpix(p);
    float* dst = g_xr + pp * 128;
    __half* dh = g_xh + pp * 128;
    const int ch = lane * 4;
    const float vv[4] = {v.x, v.y, v.z, v.w};
    #pragma unroll
    for (int e = 0; e < 4; e++) {
        dst[kperm(ch + e)] = tf32r(vv[e]);
        dh[fperm(ch + e)]  = __float2half_rn(vv[e]);
    }
}
__global__ __launch_bounds__(256)
void k0c_asum()
{
    const int p = blockIdx.x * 256 + threadIdx.x;
    const int h = (p >> 6) & 63, w = p & 63;
    float s = 0.f;
    #pragma unroll
    for (int dh = -1; dh <= 1; dh++)
        #pragma unroll
        for (int dw = -1; dw <= 1; dw++) {
            int hh = h + dh, ww = w + dw;
            if ((unsigned)hh < 64u && (unsigned)ww < 64u) s += g_sq[p + dh * 64 + dw];
        }
    g_asum[p] = s;
}

// ---- k1: tf32 yat conv. 128 threads, warp tile 64x64 (R10). ----
__global__ __launch_bounds__(128, 2)
void k1_yat(const float* __restrict__ alphap)
{
    extern __shared__ float smf[];
    const uint32_t sb = smem_u32(smf);
    const int tid = threadIdx.x, lane = tid & 31, wid = tid >> 5;
    const int wm = wid >> 1, wn = wid & 1;
    const int m_base = blockIdx.y * 128, c_base = blockIdx.x * 128;
    float* sbsum = smf + 24576;
    sbsum[tid] = g_bsum[c_base + tid];

    float acc[4][8][4];
    #pragma unroll
    for (int mi = 0; mi < 4; mi++)
        #pragma unroll
        for (int ni = 0; ni < 8; ni++)
            #pragma unroll
            for (int e = 0; e < 4; e++) acc[mi][ni][e] = 0.f;

    const int t8 = tid & 7, row0 = tid >> 3;
    const float* xb[8];
    #pragma unroll
    for (int p = 0; p < 8; p++)
        xb[p] = g_xr + padpix(m_base + row0 + 16 * p) * 128 + t8 * 4;
    const float* wb0 = g_wyT + (size_t)(c_base + row0) * K1T + t8 * 4;
    const uint32_t du0 = (uint32_t)(row0 * 128 + ((t8 ^ (2 * (row0 & 3))) * 16));

    auto stage = [&](int c, int b) {
        const int khw = c >> 2, c0 = (c & 3) * 32;
        const int dh = khw / 3 - 1, dw = khw % 3 - 1;
        const int xoff = (dh * PH + dw) * 128 + c0;
        const uint32_t base = sb + (uint32_t)b * 32768u + du0;
        const float* wsrc = wb0 + c * 32;
        #pragma unroll
        for (int p = 0; p < 8; p++) {
            cpa16(base + p * 2048u, xb[p] + xoff);
            cpa16(base + 16384u + p * 2048u, wsrc + p * (16 * K1T));
        }
        CPA_COMMIT();
    };

    stage(0, 0); stage(1, 1);
    CPA_WAIT1(); __syncthreads();
    uint2 aL[2][4], aH[2][4], bv[2][8];
    ldfrag((const char*)smf, (const char*)smf + 16384, 0, lane, wm, wn, aL[0], aH[0], bv[0]);

    int b = 0;
    for (int c = 0; c < NCH1; c++) {
        const char* As = (const char*)smf + b * 32768;
        const char* Bs = As + 16384;
        #pragma unroll
        for (int ks = 0; ks < 3; ks++) {
            ldfrag(As, Bs, ks + 1, lane, wm, wn, aL[(ks + 1) & 1], aH[(ks + 1) & 1], bv[(ks + 1) & 1]);
            do_mmas_t(acc, aL[ks & 1], aH[ks & 1], bv[ks & 1]);
        }
        if (c + 1 < NCH1) {
            CPA_WAIT0(); __syncthreads();
            int b2 = b + 2; if (b2 >= 3) b2 -= 3;
            if (c + 2 < NCH1) stage(c + 2, b2);
            int nb = b + 1; if (nb >= 3) nb -= 3;
            const char* As2 = (const char*)smf + nb * 32768;
            ldfrag(As2, As2 + 16384, 0, lane, wm, wn, aL[0], aH[0], bv[0]);
        }
        do_mmas_t(acc, aL[1], aH[1], bv[1]);
        if (++b == 3) b = 0;
    }

    const float scale = powf(16.f / log1pf(256.f), alphap[0]);
    #pragma unroll
    for (int mi = 0; mi < 4; mi++) {
        const int r0 = wm * 64 + mi * 16 + (lane >> 2);
        const int m0 = m_base + r0, m1 = m0 + 8;
        const float as0 = g_asum[m0], as1 = g_asum[m1];
        uint32_t* y0 = g_yh + padpix(m0) * 128;
        uint32_t* y1 = g_yh + padpix(m1) * 128;
        #pragma unroll
        for (int ni = 0; ni < 8; ni++) {
            const int cl = wn * 64 + ni * 8 + (lane & 3) * 2;
            const int gc = c_base + cl;
            const float bs0 = sbsum[cl], bs1 = sbsum[cl + 1];
            const float* d = acc[mi][ni];
            const float y00 = d[0] * d[0] / (as0 + bs0 - 2.f * d[0] + 1e-5f) * scale;
            const float y01 = d[1] * d[1] / (as0 + bs1 - 2.f * d[1] + 1e-5f) * scale;
            const float y10 = d[2] * d[2] / (as1 + bs0 - 2.f * d[2] + 1e-5f) * scale;
            const float y11 = d[3] * d[3] / (as1 + bs1 - 2.f * d[3] + 1e-5f) * scale;
            const int u5 = (gc >> 1) & 31, tt = u5 & 7;
            const int pos = (gc >> 6) * 32 + (u5 >> 3) * 8 + (tt & 3) * 2 + (tt >> 2);
            uint32_t h0, h1;
            asm("cvt.rn.f16x2.f32 %0, %1, %2;" : "=r"(h0) : "f"(y01), "f"(y00));
            asm("cvt.rn.f16x2.f32 %0, %1, %2;" : "=r"(h1) : "f"(y11), "f"(y10));
            y0[pos] = h0;
            y1[pos] = h1;
        }
    }
}

// ---- k2: fp16 lin conv + residual + pool. 128 threads, warp tile 64x64, K-chunk 64. ----
__global__ __launch_bounds__(128, 2)
void k2_lin(float* __restrict__ out)
{
    extern __shared__ float smf[];
    const uint32_t sb = smem_u32(smf);
    const int tid = threadIdx.x, lane = tid & 31, wid = tid >> 5;
    const int wm = wid >> 1, wn = wid & 1;
    const int m_base = blockIdx.y * 128, c_base = blockIdx.x * 128;

    float acc[4][8][4];
    #pragma unroll
    for (int mi = 0; mi < 4; mi++)
        #pragma unroll
        for (int ni = 0; ni < 8; ni++)
            #pragma unroll
            for (int e = 0; e < 4; e++) acc[mi][ni][e] = 0.f;

    const int t8 = tid & 7, row0 = tid >> 3;
    const char *yb[8], *xb2[8];
    #pragma unroll
    for (int p = 0; p < 8; p++) {
        const size_t pp = padpix(m_base + row0 + 16 * p);
        yb[p]  = (const char*)g_yh + pp * 512 + t8 * 16;
        xb2[p] = (const char*)g_xh + pp * 256 + t8 * 16;
    }
    const char* wb0 = (const char*)g_wlh + (size_t)(c_base + row0) * (K2T * 2) + t8 * 16;
    const uint32_t du0 = (uint32_t)(row0 * 128 + ((t8 ^ (2 * (row0 & 3))) * 16));

    auto stage = [&](int c, int b) {
        const uint32_t base = sb + (uint32_t)b * 32768u + du0;
        const char* wsrc = wb0 + c * 128;
        if (c < 36) {
            const int khw = c >> 2;
            const int dh = khw / 3 - 1, dw = khw % 3 - 1;
            const int yoff = (dh * PH + dw) * 512 + (c & 3) * 128;
            #pragma unroll
            for (int p = 0; p < 8; p++) {
                cpa16(base + p * 2048u, yb[p] + yoff);
                cpa16(base + 16384u + p * 2048u, wsrc + p * (16 * K2T * 2));
            }
        } else {
            const int xoff = (c - 36) * 128;
            #pragma unroll
            for (int p = 0; p < 8; p++) {
                cpa16(base + p * 2048u, xb2[p] + xoff);
                cpa16(base + 16384u + p * 2048u, wsrc + p * (16 * K2T * 2));
            }
        }
        CPA_COMMIT();
    };

    stage(0, 0); stage(1, 1);
    CPA_WAIT1(); __syncthreads();
    uint2 aL[2][4], aH[2][4], bv[2][8];
    ldfrag((const char*)smf, (const char*)smf + 16384, 0, lane, wm, wn, aL[0], aH[0], bv[0]);

    int b = 0;
    for (int c = 0; c < NCH2; c++) {
        const char* As = (const char*)smf + b * 32768;
        const char* Bs = As + 16384;
        #pragma unroll
        for (int ks = 0; ks < 3; ks++) {
            ldfrag(As, Bs, ks + 1, lane, wm, wn, aL[(ks + 1) & 1], aH[(ks + 1) & 1], bv[(ks + 1) & 1]);
            do_mmas_h(acc, aL[ks & 1], aH[ks & 1], bv[ks & 1]);
        }
        if (c + 1 < NCH2) {
            CPA_WAIT0(); __syncthreads();
            int b2 = b + 2; if (b2 >= 3) b2 -= 3;
            if (c + 2 < NCH2) stage(c + 2, b2);
            int nb = b + 1; if (nb >= 3) nb -= 3;
            const char* As2 = (const char*)smf + nb * 32768;
            ldfrag(As2, As2 + 16384, 0, lane, wm, wn, aL[0], aH[0], bv[0]);
        }
        do_mmas_h(acc, aL[1], aH[1], bv[1]);
        if (++b == 3) b = 0;
    }

    __syncthreads();
    #pragma unroll
    for (int mi = 0; mi < 4; mi++) {
        const int r0 = wm * 64 + mi * 16 + (lane >> 2);
        #pragma unroll
        for (int ni = 0; ni < 8; ni++) {
            const int cl = wn * 64 + ni * 8 + (lane & 3) * 2;
            const float* d = acc[mi][ni];
            *(float2*)(smf + r0 * 132 + cl) = make_float2(d[0], d[1]);
            *(float2*)(smf + (r0 + 8) * 132 + cl) = make_float2(d[2], d[3]);
        }
    }
    __syncthreads();
    const int n = m_base >> 12, hp = ((m_base >> 6) & 63) >> 1;
    #pragma unroll
    for (int it = 0; it < 8; it++) {
        const int idx = tid + it * 128, pw = idx >> 5, ch = (idx & 31) * 4;
        float4 a0 = *(const float4*)(smf + (2 * pw) * 132 + ch);
        float4 a1 = *(const float4*)(smf + (2 * pw + 1) * 132 + ch);
        float4 a2 = *(const float4*)(smf + (64 + 2 * pw) * 132 + ch);
        float4 a3 = *(const float4*)(smf + (64 + 2 * pw + 1) * 132 + ch);
        *(float4*)(out + ((size_t)((n * 32 + hp) * 32 + pw)) * 256 + c_base + ch) =
            make_float4(0.25f * (a0.x + a1.x + a2.x + a3.x), 0.25f * (a0.y + a1.y + a2.y + a3.y),
                        0.25f * (a0.z + a1.z + a2.z + a3.z), 0.25f * (a0.w + a1.w + a2.w + a3.w));
    }
}

extern "C" void kernel_launch(void* const* d_in, const int* in_sizes, int n_in,
                              void* d_out, int out_size)
{
    const float* x  = (const float*)d_in[0];
    const float* wy = (const float*)d_in[1];
    const float* al = (const float*)d_in[2];
    const float* wl = (const float*)d_in[3];
    const float* wp = (const float*)d_in[4];
    float* out = (float*)d_out;

    cudaFuncSetAttribute(k1_yat, cudaFuncAttributeMaxDynamicSharedMemorySize, 98816);
    cudaFuncSetAttribute(k2_lin, cudaFuncAttributeMaxDynamicSharedMemorySize, 98304);

    k0a_w<<<256, 256>>>(wy, wl, wp);
    k0b_x<<<16384, 256>>>(x);
    k0c_asum<<<512, 256>>>();
    k1_yat<<<dim3(2, 1024), 128, 98816>>>(al);
    k2_lin<<<dim3(2, 1024), 128, 98304>>>(out);
}

// round 13
// speedup vs baseline: 2.1893x; 1.2984x over previous
#include <cuda_runtime.h>
#include <cuda_fp16.h>
#include <cstdint>
#include <math.h>

#define K1T 1152
#define K2T 2432
#define NCH1 18          // 18 chunks of 64 k (9 khw x 2)
#define NCH2 38          // 38 chunks of 64 k (36 conv + 2 residual)
#define PH 66
#define PIX (PH*PH)

__device__ uint32_t g_yh[(size_t)32 * PIX * 128];   // half2 per 2 channels, halo-padded
__device__ __half   g_xh[(size_t)32 * PIX * 128];   // fp16 input, halo-padded, fperm
__device__ float    g_sq[131072];
__device__ float    g_asum[131072];
__device__ __half   g_wyh[256 * K1T];               // fp16, fperm
__device__ __half   g_wlh[256 * K2T];               // fp16, fperm
__device__ float    g_bsum[256];

__device__ __forceinline__ uint32_t smem_u32(const void* p) {
    uint32_t a;
    asm("{ .reg .u64 t; cvta.to.shared.u64 t, %1; cvt.u32.u64 %0, t; }" : "=r"(a) : "l"(p));
    return a;
}
// fp16 per-64 chunk perm on channel-pairs: unit u (=k>>1) -> b32 pos 8m+2(t&3)+(t>>2)
__device__ __forceinline__ int fperm(int k) {
    const int u = (k >> 1) & 31, m = u >> 3, t = u & 7;
    return (k & ~63) + (m * 8 + (t & 3) * 2 + (t >> 2)) * 2 + (k & 1);
}
__device__ __forceinline__ void cpa16(uint32_t dst, const void* src) {
    asm volatile("cp.async.cg.shared.global [%0], [%1], 16;" :: "r"(dst), "l"(src));
}
#define CPA_COMMIT()  asm volatile("cp.async.commit_group;" ::: "memory")
#define CPA_WAIT1()   asm volatile("cp.async.wait_group 1;" ::: "memory")
#define CPA_WAIT0()   asm volatile("cp.async.wait_group 0;" ::: "memory")

__device__ __forceinline__ void mmah(float* d, uint32_t a0, uint32_t a1, uint32_t a2, uint32_t a3,
                                     uint32_t b0, uint32_t b1) {
    asm volatile("mma.sync.aligned.m16n8k16.row.col.f32.f16.f16.f32 "
                 "{%0,%1,%2,%3}, {%4,%5,%6,%7}, {%8,%9}, {%0,%1,%2,%3};"
                 : "+f"(d[0]), "+f"(d[1]), "+f"(d[2]), "+f"(d[3])
                 : "r"(a0), "r"(a1), "r"(a2), "r"(a3), "r"(b0), "r"(b1));
}

// As/Bs 128 rows x 128B; 8B unit s at s^(4*(r&3)). Warp tile 64x64.
__device__ __forceinline__ void ldfrag(const char* As, const char* Bs, int ks, int lane,
                                       int wm, int wn, uint2* aL, uint2* aH, uint2* bv)
{
    const int r = lane >> 2, c = lane & 3;
    const int u = ((4 * ks + c) ^ (4 * (r & 3))) * 8;
    #pragma unroll
    for (int mi = 0; mi < 4; mi++) {
        const int row0 = wm * 64 + mi * 16 + r;
        aL[mi] = *(const uint2*)(As + row0 * 128 + u);
        aH[mi] = *(const uint2*)(As + (row0 + 8) * 128 + u);
    }
    #pragma unroll
    for (int ni = 0; ni < 8; ni++)
        bv[ni] = *(const uint2*)(Bs + (wn * 64 + ni * 8 + r) * 128 + u);
}
__device__ __forceinline__ void do_mmas_h(float acc[4][8][4], const uint2* aL, const uint2* aH,
                                          const uint2* bv)
{
    #pragma unroll
    for (int ni = 0; ni < 8; ni++)
        #pragma unroll
        for (int mi = 0; mi < 4; mi++)
            mmah(acc[mi][ni], aL[mi].x, aH[mi].x, aL[mi].y, aH[mi].y, bv[ni].x, bv[ni].y);
}

__device__ __forceinline__ size_t padpix(int m) {
    const int n = m >> 12, h = (m >> 6) & 63, w = m & 63;
    return (size_t)((n * PH + h + 1) * PH + (w + 1));
}

// ---- prep ----
__global__ __launch_bounds__(256)
void k0a_w(const float* __restrict__ wy, const float* __restrict__ wl, const float* __restrict__ wp)
{
    const int co = blockIdx.x, t = threadIdx.x;
    __shared__ float red[256];
    float s = 0.f;
    for (int k = t; k < K1T; k += 256) {
        float v = wy[(size_t)k * 256 + co];
        s += v * v;
        g_wyh[(size_t)co * K1T + fperm(k)] = __float2half_rn(v);
    }
    red[t] = s; __syncthreads();
    for (int o = 128; o > 0; o >>= 1) { if (t < o) red[t] += red[t + o]; __syncthreads(); }
    if (t == 0) g_bsum[co] = red[0];
    for (int k = t; k < K2T; k += 256) {
        float v = (k < 2304) ? wl[(size_t)k * 256 + co] : wp[(size_t)(k - 2304) * 256 + co];
        g_wlh[(size_t)co * K2T + fperm(k)] = __float2half_rn(v);
    }
}
__global__ __launch_bounds__(256)
void k0b_x(const float* __restrict__ x)
{
    const int p = blockIdx.x * 8 + (threadIdx.x >> 5), lane = threadIdx.x & 31;
    float4 v = *(const float4*)(x + (size_t)p * 128 + lane * 4);
    float s = v.x * v.x + v.y * v.y + v.z * v.z + v.w * v.w;
    #pragma unroll
    for (int o = 16; o > 0; o >>= 1) s += __shfl_xor_sync(0xffffffff, s, o);
    if (lane == 0) g_sq[p] = s;
    __half* dh = g_xh + padpix(p) * 128;
    const int ch = lane * 4;
    const float vv[4] = {v.x, v.y, v.z, v.w};
    #pragma unroll
    for (int e = 0; e < 4; e++)
        dh[fperm(ch + e)] = __float2half_rn(vv[e]);
}
__global__ __launch_bounds__(256)
void k0c_asum()
{
    const int p = blockIdx.x * 256 + threadIdx.x;
    const int h = (p >> 6) & 63, w = p & 63;
    float s = 0.f;
    #pragma unroll
    for (int dh = -1; dh <= 1; dh++)
        #pragma unroll
        for (int dw = -1; dw <= 1; dw++) {
            int hh = h + dh, ww = w + dw;
            if ((unsigned)hh < 64u && (unsigned)ww < 64u) s += g_sq[p + dh * 64 + dw];
        }
    g_asum[p] = s;
}

// ---- k1: fp16 yat conv. 128 threads, warp tile 64x64, K-chunk 64. ----
__global__ __launch_bounds__(128, 2)
void k1_yat(const float* __restrict__ alphap)
{
    extern __shared__ float smf[];
    const uint32_t sb = smem_u32(smf);
    const int tid = threadIdx.x, lane = tid & 31, wid = tid >> 5;
    const int wm = wid >> 1, wn = wid & 1;
    const int m_base = blockIdx.y * 128, c_base = blockIdx.x * 128;
    float* sbsum = smf + 24576;
    sbsum[tid] = g_bsum[c_base + tid];

    float acc[4][8][4];
    #pragma unroll
    for (int mi = 0; mi < 4; mi++)
        #pragma unroll
        for (int ni = 0; ni < 8; ni++)
            #pragma unroll
            for (int e = 0; e < 4; e++) acc[mi][ni][e] = 0.f;

    const int t8 = tid & 7, row0 = tid >> 3;
    const char* xb[8];
    #pragma unroll
    for (int p = 0; p < 8; p++)
        xb[p] = (const char*)g_xh + padpix(m_base + row0 + 16 * p) * 256 + t8 * 16;
    const char* wb0 = (const char*)g_wyh + (size_t)(c_base + row0) * (K1T * 2) + t8 * 16;
    const uint32_t du0 = (uint32_t)(row0 * 128 + ((t8 ^ (2 * (row0 & 3))) * 16));

    auto stage = [&](int c, int b) {
        const int khw = c >> 1;
        const int dh = khw / 3 - 1, dw = khw % 3 - 1;
        const int xoff = (dh * PH + dw) * 256 + (c & 1) * 128;
        const uint32_t base = sb + (uint32_t)b * 32768u + du0;
        const char* wsrc = wb0 + c * 128;
        #pragma unroll
        for (int p = 0; p < 8; p++) {
            cpa16(base + p * 2048u, xb[p] + xoff);
            cpa16(base + 16384u + p * 2048u, wsrc + p * (16 * K1T * 2));
        }
        CPA_COMMIT();
    };

    stage(0, 0); stage(1, 1);
    CPA_WAIT1(); __syncthreads();
    uint2 aL[2][4], aH[2][4], bv[2][8];
    ldfrag((const char*)smf, (const char*)smf + 16384, 0, lane, wm, wn, aL[0], aH[0], bv[0]);

    int b = 0;
    for (int c = 0; c < NCH1; c++) {
        const char* As = (const char*)smf + b * 32768;
        const char* Bs = As + 16384;
        #pragma unroll
        for (int ks = 0; ks < 3; ks++) {
            ldfrag(As, Bs, ks + 1, lane, wm, wn, aL[(ks + 1) & 1], aH[(ks + 1) & 1], bv[(ks + 1) & 1]);
            do_mmas_h(acc, aL[ks & 1], aH[ks & 1], bv[ks & 1]);
        }
        if (c + 1 < NCH1) {
            CPA_WAIT0(); __syncthreads();
            int b2 = b + 2; if (b2 >= 3) b2 -= 3;
            if (c + 2 < NCH1) stage(c + 2, b2);
            int nb = b + 1; if (nb >= 3) nb -= 3;
            const char* As2 = (const char*)smf + nb * 32768;
            ldfrag(As2, As2 + 16384, 0, lane, wm, wn, aL[0], aH[0], bv[0]);
        }
        do_mmas_h(acc, aL[1], aH[1], bv[1]);
        if (++b == 3) b = 0;
    }

    const float scale = powf(16.f / log1pf(256.f), alphap[0]);
    #pragma unroll
    for (int mi = 0; mi < 4; mi++) {
        const int r0 = wm * 64 + mi * 16 + (lane >> 2);
        const int m0 = m_base + r0, m1 = m0 + 8;
        const float as0 = g_asum[m0], as1 = g_asum[m1];
        uint32_t* y0 = g_yh + padpix(m0) * 128;
        uint32_t* y1 = g_yh + padpix(m1) * 128;
        #pragma unroll
        for (int ni = 0; ni < 8; ni++) {
            const int cl = wn * 64 + ni * 8 + (lane & 3) * 2;
            const int gc = c_base + cl;
            const float bs0 = sbsum[cl], bs1 = sbsum[cl + 1];
            const float* d = acc[mi][ni];
            const float y00 = d[0] * d[0] / (as0 + bs0 - 2.f * d[0] + 1e-5f) * scale;
            const float y01 = d[1] * d[1] / (as0 + bs1 - 2.f * d[1] + 1e-5f) * scale;
            const float y10 = d[2] * d[2] / (as1 + bs0 - 2.f * d[2] + 1e-5f) * scale;
            const float y11 = d[3] * d[3] / (as1 + bs1 - 2.f * d[3] + 1e-5f) * scale;
            const int u5 = (gc >> 1) & 31, tt = u5 & 7;
            const int pos = (gc >> 6) * 32 + (u5 >> 3) * 8 + (tt & 3) * 2 + (tt >> 2);
            uint32_t h0, h1;
            asm("cvt.rn.f16x2.f32 %0, %1, %2;" : "=r"(h0) : "f"(y01), "f"(y00));
            asm("cvt.rn.f16x2.f32 %0, %1, %2;" : "=r"(h1) : "f"(y11), "f"(y10));
            y0[pos] = h0;
            y1[pos] = h1;
        }
    }
}

// ---- k2: fp16 lin conv + residual + pool. 128 threads, warp tile 64x64, K-chunk 64. ----
__global__ __launch_bounds__(128, 2)
void k2_lin(float* __restrict__ out)
{
    extern __shared__ float smf[];
    const uint32_t sb = smem_u32(smf);
    const int tid = threadIdx.x, lane = tid & 31, wid = tid >> 5;
    const int wm = wid >> 1, wn = wid & 1;
    const int m_base = blockIdx.y * 128, c_base = blockIdx.x * 128;

    float acc[4][8][4];
    #pragma unroll
    for (int mi = 0; mi < 4; mi++)
        #pragma unroll
        for (int ni = 0; ni < 8; ni++)
            #pragma unroll
            for (int e = 0; e < 4; e++) acc[mi][ni][e] = 0.f;

    const int t8 = tid & 7, row0 = tid >> 3;
    const char *yb[8], *xb2[8];
    #pragma unroll
    for (int p = 0; p < 8; p++) {
        const size_t pp = padpix(m_base + row0 + 16 * p);
        yb[p]  = (const char*)g_yh + pp * 512 + t8 * 16;
        xb2[p] = (const char*)g_xh + pp * 256 + t8 * 16;
    }
    const char* wb0 = (const char*)g_wlh + (size_t)(c_base + row0) * (K2T * 2) + t8 * 16;
    const uint32_t du0 = (uint32_t)(row0 * 128 + ((t8 ^ (2 * (row0 & 3))) * 16));

    auto stage = [&](int c, int b) {
        const uint32_t base = sb + (uint32_t)b * 32768u + du0;
        const char* wsrc = wb0 + c * 128;
        if (c < 36) {
            const int khw = c >> 2;
            const int dh = khw / 3 - 1, dw = khw % 3 - 1;
            const int yoff = (dh * PH + dw) * 512 + (c & 3) * 128;
            #pragma unroll
            for (int p = 0; p < 8; p++) {
                cpa16(base + p * 2048u, yb[p] + yoff);
                cpa16(base + 16384u + p * 2048u, wsrc + p * (16 * K2T * 2));
            }
        } else {
            const int xoff = (c - 36) * 128;
            #pragma unroll
            for (int p = 0; p < 8; p++) {
                cpa16(base + p * 2048u, xb2[p] + xoff);
                cpa16(base + 16384u + p * 2048u, wsrc + p * (16 * K2T * 2));
            }
        }
        CPA_COMMIT();
    };

    stage(0, 0); stage(1, 1);
    CPA_WAIT1(); __syncthreads();
    uint2 aL[2][4], aH[2][4], bv[2][8];
    ldfrag((const char*)smf, (const char*)smf + 16384, 0, lane, wm, wn, aL[0], aH[0], bv[0]);

    int b = 0;
    for (int c = 0; c < NCH2; c++) {
        const char* As = (const char*)smf + b * 32768;
        const char* Bs = As + 16384;
        #pragma unroll
        for (int ks = 0; ks < 3; ks++) {
            ldfrag(As, Bs, ks + 1, lane, wm, wn, aL[(ks + 1) & 1], aH[(ks + 1) & 1], bv[(ks + 1) & 1]);
            do_mmas_h(acc, aL[ks & 1], aH[ks & 1], bv[ks & 1]);
        }
        if (c + 1 < NCH2) {
            CPA_WAIT0(); __syncthreads();
            int b2 = b + 2; if (b2 >= 3) b2 -= 3;
            if (c + 2 < NCH2) stage(c + 2, b2);
            int nb = b + 1; if (nb >= 3) nb -= 3;
            const char* As2 = (const char*)smf + nb * 32768;
            ldfrag(As2, As2 + 16384, 0, lane, wm, wn, aL[0], aH[0], bv[0]);
        }
        do_mmas_h(acc, aL[1], aH[1], bv[1]);
        if (++b == 3) b = 0;
    }

    __syncthreads();
    #pragma unroll
    for (int mi = 0; mi < 4; mi++) {
        const int r0 = wm * 64 + mi * 16 + (lane >> 2);
        #pragma unroll
        for (int ni = 0; ni < 8; ni++) {
            const int cl = wn * 64 + ni * 8 + (lane & 3) * 2;
            const float* d = acc[mi][ni];
            *(float2*)(smf + r0 * 132 + cl) = make_float2(d[0], d[1]);
            *(float2*)(smf + (r0 + 8) * 132 + cl) = make_float2(d[2], d[3]);
        }
    }
    __syncthreads();
    const int n = m_base >> 12, hp = ((m_base >> 6) & 63) >> 1;
    #pragma unroll
    for (int it = 0; it < 8; it++) {
        const int idx = tid + it * 128, pw = idx >> 5, ch = (idx & 31) * 4;
        float4 a0 = *(const float4*)(smf + (2 * pw) * 132 + ch);
        float4 a1 = *(const float4*)(smf + (2 * pw + 1) * 132 + ch);
        float4 a2 = *(const float4*)(smf + (64 + 2 * pw) * 132 + ch);
        float4 a3 = *(const float4*)(smf + (64 + 2 * pw + 1) * 132 + ch);
        *(float4*)(out + ((size_t)((n * 32 + hp) * 32 + pw)) * 256 + c_base + ch) =
            make_float4(0.25f * (a0.x + a1.x + a2.x + a3.x), 0.25f * (a0.y + a1.y + a2.y + a3.y),
                        0.25f * (a0.z + a1.z + a2.z + a3.z), 0.25f * (a0.w + a1.w + a2.w + a3.w));
    }
}

extern "C" void kernel_launch(void* const* d_in, const int* in_sizes, int n_in,
                              void* d_out, int out_size)
{
    const float* x  = (const float*)d_in[0];
    const float* wy = (const float*)d_in[1];
    const float* al = (const float*)d_in[2];
    const float* wl = (const float*)d_in[3];
    const float* wp = (const float*)d_in[4];
    float* out = (float*)d_out;

    cudaFuncSetAttribute(k1_yat, cudaFuncAttributeMaxDynamicSharedMemorySize, 98816);
    cudaFuncSetAttribute(k2_lin, cudaFuncAttributeMaxDynamicSharedMemorySize, 98304);

    k0a_w<<<256, 256>>>(wy, wl, wp);
    k0b_x<<<16384, 256>>>(x);
    k0c_asum<<<512, 256>>>();
    k1_yat<<<dim3(2, 1024), 128, 98816>>>(al);
    k2_lin<<<dim3(2, 1024), 128, 98304>>>(out);
}

// round 14
// speedup vs baseline: 2.3170x; 1.0583x over previous
#include <cuda_runtime.h>
#include <cuda_fp16.h>
#include <cstdint>
#include <math.h>

#define K1T 1152
#define K2T 2432
#define NCH1 18          // 18 chunks of 64 k
#define NCH2 38          // 36 conv + 2 residual
#define PH 66
#define PIX (PH*PH)

__device__ uint32_t g_yh[(size_t)32 * PIX * 128];   // half2 per channel pair, natural order, halo-padded
__device__ __half   g_xh[(size_t)32 * PIX * 128];   // fp16 input, natural order, halo-padded
__device__ float    g_sq[131072];
__device__ float    g_asum[131072];
__device__ __half   g_wyh[256 * K1T];               // K-major natural
__device__ __half   g_wlh[256 * K2T];               // K-major natural [wl|wp]
__device__ float    g_bsum[256];

__device__ __forceinline__ uint32_t smem_u32(const void* p) {
    uint32_t a;
    asm("{ .reg .u64 t; cvta.to.shared.u64 t, %1; cvt.u32.u64 %0, t; }" : "=r"(a) : "l"(p));
    return a;
}
__device__ __forceinline__ void cpa16(uint32_t dst, const void* src) {
    asm volatile("cp.async.cg.shared.global [%0], [%1], 16;" :: "r"(dst), "l"(src));
}
#define CPA_COMMIT()  asm volatile("cp.async.commit_group;" ::: "memory")
#define CPA_WAIT1()   asm volatile("cp.async.wait_group 1;" ::: "memory")
#define CPA_WAIT0()   asm volatile("cp.async.wait_group 0;" ::: "memory")

__device__ __forceinline__ void ldsm4(uint32_t addr, uint32_t* r) {
    asm volatile("ldmatrix.sync.aligned.m8n8.x4.shared.b16 {%0,%1,%2,%3}, [%4];"
                 : "=r"(r[0]), "=r"(r[1]), "=r"(r[2]), "=r"(r[3]) : "r"(addr));
}
__device__ __forceinline__ void mmah(float* d, uint32_t a0, uint32_t a1, uint32_t a2, uint32_t a3,
                                     uint32_t b0, uint32_t b1) {
    asm volatile("mma.sync.aligned.m16n8k16.row.col.f32.f16.f16.f32 "
                 "{%0,%1,%2,%3}, {%4,%5,%6,%7}, {%8,%9}, {%0,%1,%2,%3};"
                 : "+f"(d[0]), "+f"(d[1]), "+f"(d[2]), "+f"(d[3])
                 : "r"(a0), "r"(a1), "r"(a2), "r"(a3), "r"(b0), "r"(b1));
}

// Tiles: 128 rows x 128B (64 fp16), 16B unit u of row r stored at u^(r&7).
// Fragments via ldmatrix.x4: A mi-tile rows wm*64+mi*16+(lane&15), unit 2ks+(lane>>4);
// B pairs n8-tiles 2j,2j+1 the same way.
__device__ __forceinline__ void do_mmas(float acc[4][8][4], uint32_t fa[4][4], uint32_t fb[4][4])
{
    #pragma unroll
    for (int j = 0; j < 4; j++)
        #pragma unroll
        for (int mi = 0; mi < 4; mi++) {
            mmah(acc[mi][2 * j],     fa[mi][0], fa[mi][1], fa[mi][2], fa[mi][3], fb[j][0], fb[j][2]);
            mmah(acc[mi][2 * j + 1], fa[mi][0], fa[mi][1], fa[mi][2], fa[mi][3], fb[j][1], fb[j][3]);
        }
}

__device__ __forceinline__ size_t padpix(int m) {
    const int n = m >> 12, h = (m >> 6) & 63, w = m & 63;
    return (size_t)((n * PH + h + 1) * PH + (w + 1));
}

// ---- prep ----
__global__ __launch_bounds__(256)
void k0a_w(const float* __restrict__ wy, const float* __restrict__ wl, const float* __restrict__ wp)
{
    const int co = blockIdx.x, t = threadIdx.x;
    __shared__ float red[256];
    float s = 0.f;
    for (int k = t; k < K1T; k += 256) {
        float v = wy[(size_t)k * 256 + co];
        s += v * v;
        g_wyh[(size_t)co * K1T + k] = __float2half_rn(v);
    }
    red[t] = s; __syncthreads();
    for (int o = 128; o > 0; o >>= 1) { if (t < o) red[t] += red[t + o]; __syncthreads(); }
    if (t == 0) g_bsum[co] = red[0];
    for (int k = t; k < K2T; k += 256) {
        float v = (k < 2304) ? wl[(size_t)k * 256 + co] : wp[(size_t)(k - 2304) * 256 + co];
        g_wlh[(size_t)co * K2T + k] = __float2half_rn(v);
    }
}
__global__ __launch_bounds__(256)
void k0b_x(const float* __restrict__ x)
{
    const int p = blockIdx.x * 8 + (threadIdx.x >> 5), lane = threadIdx.x & 31;
    float4 v = *(const float4*)(x + (size_t)p * 128 + lane * 4);
    float s = v.x * v.x + v.y * v.y + v.z * v.z + v.w * v.w;
    #pragma unroll
    for (int o = 16; o > 0; o >>= 1) s += __shfl_xor_sync(0xffffffff, s, o);
    if (lane == 0) g_sq[p] = s;
    __half2* dh = (__half2*)(g_xh + padpix(p) * 128 + lane * 4);
    dh[0] = __floats2half2_rn(v.x, v.y);
    dh[1] = __floats2half2_rn(v.z, v.w);
}
__global__ __launch_bounds__(256)
void k0c_asum()
{
    const int p = blockIdx.x * 256 + threadIdx.x;
    const int h = (p >> 6) & 63, w = p & 63;
    float s = 0.f;
    #pragma unroll
    for (int dh = -1; dh <= 1; dh++)
        #pragma unroll
        for (int dw = -1; dw <= 1; dw++) {
            int hh = h + dh, ww = w + dw;
            if ((unsigned)hh < 64u && (unsigned)ww < 64u) s += g_sq[p + dh * 64 + dw];
        }
    g_asum[p] = s;
}

// ---- k1: fp16 yat conv, ldmatrix fragments ----
__global__ __launch_bounds__(128, 2)
void k1_yat(const float* __restrict__ alphap)
{
    extern __shared__ float smf[];
    const uint32_t sb = smem_u32(smf);
    const int tid = threadIdx.x, lane = tid & 31, wid = tid >> 5;
    const int wm = wid >> 1, wn = wid & 1;
    const int m_base = blockIdx.y * 128, c_base = blockIdx.x * 128;
    float* sbsum = smf + 24576;
    sbsum[tid] = g_bsum[c_base + tid];

    float acc[4][8][4];
    #pragma unroll
    for (int mi = 0; mi < 4; mi++)
        #pragma unroll
        for (int ni = 0; ni < 8; ni++)
            #pragma unroll
            for (int e = 0; e < 4; e++) acc[mi][ni][e] = 0.f;

    // ldmatrix lane addressing
    const int rl = lane & 15, lh = lane >> 4, sw = rl & 7;
    uint32_t aoff[4], boff[4];
    #pragma unroll
    for (int i = 0; i < 4; i++) {
        aoff[i] = (uint32_t)((wm * 64 + i * 16 + rl) * 128);
        boff[i] = (uint32_t)((wn * 64 + i * 16 + rl) * 128) + 16384u;
    }

    const int t8 = tid & 7, row0 = tid >> 3;
    const char* xb[8];
    #pragma unroll
    for (int p = 0; p < 8; p++)
        xb[p] = (const char*)g_xh + padpix(m_base + row0 + 16 * p) * 256 + t8 * 16;
    const char* wb0 = (const char*)g_wyh + (size_t)(c_base + row0) * (K1T * 2) + t8 * 16;
    const uint32_t du0 = (uint32_t)(row0 * 128 + ((t8 ^ (row0 & 7)) * 16));

    auto stage = [&](int c, int b) {
        const int khw = c >> 1;
        const int dh = khw / 3 - 1, dw = khw % 3 - 1;
        const int xoff = (dh * PH + dw) * 256 + (c & 1) * 128;
        const uint32_t base = sb + (uint32_t)b * 32768u + du0;
        const char* wsrc = wb0 + c * 128;
        #pragma unroll
        for (int p = 0; p < 8; p++) {
            cpa16(base + p * 2048u, xb[p] + xoff);
            cpa16(base + 16384u + p * 2048u, wsrc + p * (16 * K1T * 2));
        }
        CPA_COMMIT();
    };

    uint32_t fa[2][4][4], fb[2][4][4];
    auto ldfrag = [&](uint32_t bufbase, int ks, int r) {
        const uint32_t off = (uint32_t)(((2 * ks + lh) ^ sw) * 16);
        #pragma unroll
        for (int i = 0; i < 4; i++) ldsm4(bufbase + aoff[i] + off, fa[r][i]);
        #pragma unroll
        for (int i = 0; i < 4; i++) ldsm4(bufbase + boff[i] + off, fb[r][i]);
    };

    stage(0, 0); stage(1, 1);
    CPA_WAIT1(); __syncthreads();
    ldfrag(sb, 0, 0);

    int b = 0;
    for (int c = 0; c < NCH1; c++) {
        const uint32_t bufb = sb + (uint32_t)b * 32768u;
        #pragma unroll
        for (int ks = 0; ks < 3; ks++) {
            ldfrag(bufb, ks + 1, (ks + 1) & 1);
            do_mmas(acc, fa[ks & 1], fb[ks & 1]);
        }
        if (c + 1 < NCH1) {
            CPA_WAIT0(); __syncthreads();
            int b2 = b + 2; if (b2 >= 3) b2 -= 3;
            if (c + 2 < NCH1) stage(c + 2, b2);
            int nb = b + 1; if (nb >= 3) nb -= 3;
            ldfrag(sb + (uint32_t)nb * 32768u, 0, 0);
        }
        do_mmas(acc, fa[1], fb[1]);
        if (++b == 3) b = 0;
    }

    const float scale = powf(16.f / log1pf(256.f), alphap[0]);
    #pragma unroll
    for (int mi = 0; mi < 4; mi++) {
        const int r0 = wm * 64 + mi * 16 + (lane >> 2);
        const int m0 = m_base + r0, m1 = m0 + 8;
        const float as0 = g_asum[m0], as1 = g_asum[m1];
        uint32_t* y0 = g_yh + padpix(m0) * 128;
        uint32_t* y1 = g_yh + padpix(m1) * 128;
        #pragma unroll
        for (int ni = 0; ni < 8; ni++) {
            const int cl = wn * 64 + ni * 8 + (lane & 3) * 2;
            const float bs0 = sbsum[cl], bs1 = sbsum[cl + 1];
            const float* d = acc[mi][ni];
            const float y00 = d[0] * d[0] / (as0 + bs0 - 2.f * d[0] + 1e-5f) * scale;
            const float y01 = d[1] * d[1] / (as0 + bs1 - 2.f * d[1] + 1e-5f) * scale;
            const float y10 = d[2] * d[2] / (as1 + bs0 - 2.f * d[2] + 1e-5f) * scale;
            const float y11 = d[3] * d[3] / (as1 + bs1 - 2.f * d[3] + 1e-5f) * scale;
            const int pos = (c_base + cl) >> 1;
            uint32_t h0, h1;
            asm("cvt.rn.f16x2.f32 %0, %1, %2;" : "=r"(h0) : "f"(y01), "f"(y00));
            asm("cvt.rn.f16x2.f32 %0, %1, %2;" : "=r"(h1) : "f"(y11), "f"(y10));
            y0[pos] = h0;
            y1[pos] = h1;
        }
    }
}

// ---- k2: fp16 lin conv + residual + pool, ldmatrix fragments ----
__global__ __launch_bounds__(128, 2)
void k2_lin(float* __restrict__ out)
{
    extern __shared__ float smf[];
    const uint32_t sb = smem_u32(smf);
    const int tid = threadIdx.x, lane = tid & 31, wid = tid >> 5;
    const int wm = wid >> 1, wn = wid & 1;
    const int m_base = blockIdx.y * 128, c_base = blockIdx.x * 128;

    float acc[4][8][4];
    #pragma unroll
    for (int mi = 0; mi < 4; mi++)
        #pragma unroll
        for (int ni = 0; ni < 8; ni++)
            #pragma unroll
            for (int e = 0; e < 4; e++) acc[mi][ni][e] = 0.f;

    const int rl = lane & 15, lh = lane >> 4, sw = rl & 7;
    uint32_t aoff[4], boff[4];
    #pragma unroll
    for (int i = 0; i < 4; i++) {
        aoff[i] = (uint32_t)((wm * 64 + i * 16 + rl) * 128);
        boff[i] = (uint32_t)((wn * 64 + i * 16 + rl) * 128) + 16384u;
    }

    const int t8 = tid & 7, row0 = tid >> 3;
    const char *yb[8], *xb2[8];
    #pragma unroll
    for (int p = 0; p < 8; p++) {
        const size_t pp = padpix(m_base + row0 + 16 * p);
        yb[p]  = (const char*)g_yh + pp * 512 + t8 * 16;
        xb2[p] = (const char*)g_xh + pp * 256 + t8 * 16;
    }
    const char* wb0 = (const char*)g_wlh + (size_t)(c_base + row0) * (K2T * 2) + t8 * 16;
    const uint32_t du0 = (uint32_t)(row0 * 128 + ((t8 ^ (row0 & 7)) * 16));

    auto stage = [&](int c, int b) {
        const uint32_t base = sb + (uint32_t)b * 32768u + du0;
        const char* wsrc = wb0 + c * 128;
        if (c < 36) {
            const int khw = c >> 2;
            const int dh = khw / 3 - 1, dw = khw % 3 - 1;
            const int yoff = (dh * PH + dw) * 512 + (c & 3) * 128;
            #pragma unroll
            for (int p = 0; p < 8; p++) {
                cpa16(base + p * 2048u, yb[p] + yoff);
                cpa16(base + 16384u + p * 2048u, wsrc + p * (16 * K2T * 2));
            }
        } else {
            const int xoff = (c - 36) * 128;
            #pragma unroll
            for (int p = 0; p < 8; p++) {
                cpa16(base + p * 2048u, xb2[p] + xoff);
                cpa16(base + 16384u + p * 2048u, wsrc + p * (16 * K2T * 2));
            }
        }
        CPA_COMMIT();
    };

    uint32_t fa[2][4][4], fb[2][4][4];
    auto ldfrag = [&](uint32_t bufbase, int ks, int r) {
        const uint32_t off = (uint32_t)(((2 * ks + lh) ^ sw) * 16);
        #pragma unroll
        for (int i = 0; i < 4; i++) ldsm4(bufbase + aoff[i] + off, fa[r][i]);
        #pragma unroll
        for (int i = 0; i < 4; i++) ldsm4(bufbase + boff[i] + off, fb[r][i]);
    };

    stage(0, 0); stage(1, 1);
    CPA_WAIT1(); __syncthreads();
    ldfrag(sb, 0, 0);

    int b = 0;
    for (int c = 0; c < NCH2; c++) {
        const uint32_t bufb = sb + (uint32_t)b * 32768u;
        #pragma unroll
        for (int ks = 0; ks < 3; ks++) {
            ldfrag(bufb, ks + 1, (ks + 1) & 1);
            do_mmas(acc, fa[ks & 1], fb[ks & 1]);
        }
        if (c + 1 < NCH2) {
            CPA_WAIT0(); __syncthreads();
            int b2 = b + 2; if (b2 >= 3) b2 -= 3;
            if (c + 2 < NCH2) stage(c + 2, b2);
            int nb = b + 1; if (nb >= 3) nb -= 3;
            ldfrag(sb + (uint32_t)nb * 32768u, 0, 0);
        }
        do_mmas(acc, fa[1], fb[1]);
        if (++b == 3) b = 0;
    }

    __syncthreads();
    #pragma unroll
    for (int mi = 0; mi < 4; mi++) {
        const int r0 = wm * 64 + mi * 16 + (lane >> 2);
        #pragma unroll
        for (int ni = 0; ni < 8; ni++) {
            const int cl = wn * 64 + ni * 8 + (lane & 3) * 2;
            const float* d = acc[mi][ni];
            *(float2*)(smf + r0 * 132 + cl) = make_float2(d[0], d[1]);
            *(float2*)(smf + (r0 + 8) * 132 + cl) = make_float2(d[2], d[3]);
        }
    }
    __syncthreads();
    const int n = m_base >> 12, hp = ((m_base >> 6) & 63) >> 1;
    #pragma unroll
    for (int it = 0; it < 8; it++) {
        const int idx = tid + it * 128, pw = idx >> 5, ch = (idx & 31) * 4;
        float4 a0 = *(const float4*)(smf + (2 * pw) * 132 + ch);
        float4 a1 = *(const float4*)(smf + (2 * pw + 1) * 132 + ch);
        float4 a2 = *(const float4*)(smf + (64 + 2 * pw) * 132 + ch);
        float4 a3 = *(const float4*)(smf + (64 + 2 * pw + 1) * 132 + ch);
        *(float4*)(out + ((size_t)((n * 32 + hp) * 32 + pw)) * 256 + c_base + ch) =
            make_float4(0.25f * (a0.x + a1.x + a2.x + a3.x), 0.25f * (a0.y + a1.y + a2.y + a3.y),
                        0.25f * (a0.z + a1.z + a2.z + a3.z), 0.25f * (a0.w + a1.w + a2.w + a3.w));
    }
}

extern "C" void kernel_launch(void* const* d_in, const int* in_sizes, int n_in,
                              void* d_out, int out_size)
{
    const float* x  = (const float*)d_in[0];
    const float* wy = (const float*)d_in[1];
    const float* al = (const float*)d_in[2];
    const float* wl = (const float*)d_in[3];
    const float* wp = (const float*)d_in[4];
    float* out = (float*)d_out;

    cudaFuncSetAttribute(k1_yat, cudaFuncAttributeMaxDynamicSharedMemorySize, 98816);
    cudaFuncSetAttribute(k2_lin, cudaFuncAttributeMaxDynamicSharedMemorySize, 98304);

    k0a_w<<<256, 256>>>(wy, wl, wp);
    k0b_x<<<16384, 256>>>(x);
    k0c_asum<<<512, 256>>>();
    k1_yat<<<dim3(2, 1024), 128, 98816>>>(al);
    k2_lin<<<dim3(2, 1024), 128, 98304>>>(out);
}